// round 8
// baseline (speedup 1.0000x reference)
#include <cuda_runtime.h>

#define N_NODES 50000
#define N_EDGES 1600000
#define N_LABEL 200000
#define IN_C    128
#define HID1    256
#define HID2    32

// fused GEMM smem layout (32-bit words)
#define AS_W   (128 * 36)     // S1 tile [128][36 stride]
#define BS_W   (32 * 264)     // W1 tile [32][264 stride]
#define HS_W   (128 * 260)    // h1 tile [128][260 stride]
#define W2_W   (256 * 36)     // W2     [256][36 stride]
#define SMEM_WORDS (AS_W + BS_W + HS_W + W2_W)     // 55552 w = 222208 B

// ---------------- device scratch ----------------
__device__ __align__(256) int   g_cnt   [N_NODES];
__device__ __align__(256) int   g_rowptr[N_NODES + 1];
__device__ __align__(256) int   g_cursor[N_NODES];
__device__ __align__(256) int   g_csrc  [N_EDGES];
__device__ __align__(256) float g_dinv  [N_NODES];
__device__ __align__(256) float g_S1    [N_NODES * IN_C];
__device__ __align__(256) float g_ts    [N_NODES * HID2];
__device__ __align__(256) float g_z     [N_NODES * HID2];

// ---------------- tf32 helpers ----------------
__device__ __forceinline__ unsigned f2tf32(float f) {
    unsigned r;
    asm("cvt.rna.tf32.f32 %0, %1;" : "=r"(r) : "f"(f));
    return r;
}
__device__ __forceinline__ void mma_tf32(float* c, unsigned a0, unsigned a1,
                                         unsigned a2, unsigned a3,
                                         unsigned b0, unsigned b1) {
    asm volatile(
        "mma.sync.aligned.m16n8k8.row.col.f32.tf32.tf32.f32 "
        "{%0,%1,%2,%3}, {%4,%5,%6,%7}, {%8,%9}, {%0,%1,%2,%3};"
        : "+f"(c[0]), "+f"(c[1]), "+f"(c[2]), "+f"(c[3])
        : "r"(a0), "r"(a1), "r"(a2), "r"(a3), "r"(b0), "r"(b1));
}

// ---------------- CSR build ----------------
__global__ void k_zero_cnt() {
    int i = blockIdx.x * blockDim.x + threadIdx.x;
    if (i < N_NODES) g_cnt[i] = 0;
}

__global__ void k_hist(const int* __restrict__ ei) {
    int e = blockIdx.x * blockDim.x + threadIdx.x;
    if (e < N_EDGES) atomicAdd(&g_cnt[ei[N_EDGES + e]], 1);
}

// single-block scan: 1024 threads x 49 nodes each
__global__ void k_scan_all() {
    __shared__ int sh[1024];
    const int t = threadIdx.x;
    const int beg = t * 49;
    const int end = (beg + 49 < N_NODES) ? beg + 49 : N_NODES;
    int s = 0;
    for (int i = beg; i < end; i++) s += g_cnt[i];
    sh[t] = s;
    __syncthreads();
#pragma unroll
    for (int off = 1; off < 1024; off <<= 1) {
        int v = (t >= off) ? sh[t - off] : 0;
        __syncthreads();
        sh[t] += v;
        __syncthreads();
    }
    int run = sh[t] - s;     // exclusive prefix
    for (int i = beg; i < end; i++) {
        int c = g_cnt[i];
        g_rowptr[i] = run;
        g_cursor[i] = run;
        g_dinv[i]   = rsqrtf((float)(c + 1));
        run += c;
    }
    if (t == 1023) g_rowptr[N_NODES] = N_EDGES;
}

__global__ void k_fill(const int* __restrict__ ei) {
    int e = blockIdx.x * blockDim.x + threadIdx.x;
    if (e < N_EDGES) {
        int dst = ei[N_EDGES + e];
        int pos = atomicAdd(&g_cursor[dst], 1);
        g_csrc[pos] = ei[e];
    }
}

// ---------------- conv1 gather: S1[i] = dinv[i]*x[i] + sum dinv[src]*x[src]
__global__ void k_agg1(const float* __restrict__ x) {
    int w = (blockIdx.x * blockDim.x + threadIdx.x) >> 5;
    if (w >= N_NODES) return;
    int lane = threadIdx.x & 31;
    int beg = g_rowptr[w], end = g_rowptr[w + 1];
    const float4* xv = (const float4*)x;

    float dw = g_dinv[w];
    float4 s = xv[w * 32 + lane];
    float4 acc = make_float4(dw * s.x, dw * s.y, dw * s.z, dw * s.w);

    int j = beg;
    for (; j + 3 < end; j += 4) {
        int s0 = g_csrc[j], s1 = g_csrc[j + 1], s2 = g_csrc[j + 2], s3 = g_csrc[j + 3];
        float d0 = g_dinv[s0], d1 = g_dinv[s1], d2 = g_dinv[s2], d3 = g_dinv[s3];
        float4 v0 = xv[s0 * 32 + lane];
        float4 v1 = xv[s1 * 32 + lane];
        float4 v2 = xv[s2 * 32 + lane];
        float4 v3 = xv[s3 * 32 + lane];
        acc.x += d0*v0.x; acc.y += d0*v0.y; acc.z += d0*v0.z; acc.w += d0*v0.w;
        acc.x += d1*v1.x; acc.y += d1*v1.y; acc.z += d1*v1.z; acc.w += d1*v1.w;
        acc.x += d2*v2.x; acc.y += d2*v2.y; acc.z += d2*v2.z; acc.w += d2*v2.w;
        acc.x += d3*v3.x; acc.y += d3*v3.y; acc.z += d3*v3.z; acc.w += d3*v3.w;
    }
    for (; j < end; j++) {
        int sj = g_csrc[j];
        float dj = g_dinv[sj];
        float4 v = xv[sj * 32 + lane];
        acc.x += dj*v.x; acc.y += dj*v.y; acc.z += dj*v.z; acc.w += dj*v.w;
    }
    ((float4*)g_S1)[w * 32 + lane] = acc;
}

// ---------------- fused GEMM1+GEMM2: ts = dinv*(relu(dinv*(S1@W1)+b1) @ W2)
// 512 thr = 16 warps; BM=128 BN=256 BK=32; GEMM1 warp grid 4M x 4N (warp 32x64)
__global__ __launch_bounds__(512, 1)
void k_gemm12(const float* __restrict__ W1, const float* __restrict__ b1,
              const float* __restrict__ W2) {
    extern __shared__ unsigned sm[];
    unsigned* As  = sm;                       // S1 tile [128][36]
    unsigned* Bs  = sm + AS_W;                // W1 tile [32][264]
    unsigned* Hs  = sm + AS_W + BS_W;         // h1 tile [128][260]
    unsigned* W2s = sm + AS_W + BS_W + HS_W;  // W2 [256][36]

    const int tid = threadIdx.x;
    const int warpId = tid >> 5, lane = tid & 31;
    const int gid = lane >> 2, tg = lane & 3;
    const int tileM = blockIdx.x * 128;
    const int warpM = warpId & 3, warpN = warpId >> 2;

    // preload W2 (256x32) into W2s — used only after GEMM1
#pragma unroll
    for (int i = 0; i < 4; i++) {
        int f = tid + i * 512;
        int k = f >> 3;
        int n4 = (f & 7) * 4;
        float4 v = *(const float4*)&W2[k * HID2 + n4];
        *(uint4*)&W2s[k * 36 + n4] =
            make_uint4(f2tf32(v.x), f2tf32(v.y), f2tf32(v.z), f2tf32(v.w));
    }

    float acc[2][8][4] = {};

    for (int k0 = 0; k0 < IN_C; k0 += 32) {
        // A tile 128x32: 8 elems/thread = 2 float4
#pragma unroll
        for (int i = 0; i < 2; i++) {
            int idx = tid + i * 512;
            int r   = idx >> 3;
            int c0  = (idx & 7) * 4;
            int grow = tileM + r;
            float4 v = make_float4(0.f,0.f,0.f,0.f);
            if (grow < N_NODES) v = *(const float4*)&g_S1[grow * IN_C + k0 + c0];
            *(uint4*)&As[r * 36 + c0] =
                make_uint4(f2tf32(v.x), f2tf32(v.y), f2tf32(v.z), f2tf32(v.w));
        }
        // B tile 32x256: 16 elems/thread = 4 float4
#pragma unroll
        for (int i = 0; i < 4; i++) {
            int idx = tid + i * 512;
            int r   = idx >> 6;
            int c   = (idx & 63) * 4;
            float4 v = *(const float4*)&W1[(k0 + r) * HID1 + c];
            *(uint4*)&Bs[r * 264 + c] =
                make_uint4(f2tf32(v.x), f2tf32(v.y), f2tf32(v.z), f2tf32(v.w));
        }
        __syncthreads();
#pragma unroll
        for (int ks = 0; ks < 32; ks += 8) {
            unsigned a[2][4];
#pragma unroll
            for (int mt = 0; mt < 2; mt++) {
                int rb = warpM * 32 + mt * 16;
                a[mt][0] = As[(rb + gid    ) * 36 + ks + tg    ];
                a[mt][1] = As[(rb + gid + 8) * 36 + ks + tg    ];
                a[mt][2] = As[(rb + gid    ) * 36 + ks + tg + 4];
                a[mt][3] = As[(rb + gid + 8) * 36 + ks + tg + 4];
            }
#pragma unroll
            for (int nt = 0; nt < 8; nt++) {
                int cb = warpN * 64 + nt * 8;
                unsigned b0 = Bs[(ks + tg    ) * 264 + cb + gid];
                unsigned b1v= Bs[(ks + tg + 4) * 264 + cb + gid];
                mma_tf32(acc[0][nt], a[0][0], a[0][1], a[0][2], a[0][3], b0, b1v);
                mma_tf32(acc[1][nt], a[1][0], a[1][1], a[1][2], a[1][3], b0, b1v);
            }
        }
        __syncthreads();
    }

    // epilogue1: h1 = relu(dinv*acc + b1) -> Hs (tf32)
#pragma unroll
    for (int mt = 0; mt < 2; mt++) {
        int r0 = warpM * 32 + mt * 16 + gid;
        int r1 = r0 + 8;
        int n0 = tileM + r0, n1 = tileM + r1;
        bool v0 = n0 < N_NODES, v1 = n1 < N_NODES;
        float d0 = v0 ? g_dinv[n0] : 0.f;
        float d1 = v1 ? g_dinv[n1] : 0.f;
#pragma unroll
        for (int nt = 0; nt < 8; nt++) {
            int c = warpN * 64 + nt * 8 + tg * 2;
            float bb0 = b1[c], bb1 = b1[c + 1];
            float h00 = v0 ? fmaxf(d0 * acc[mt][nt][0] + bb0, 0.f) : 0.f;
            float h01 = v0 ? fmaxf(d0 * acc[mt][nt][1] + bb1, 0.f) : 0.f;
            float h10 = v1 ? fmaxf(d1 * acc[mt][nt][2] + bb0, 0.f) : 0.f;
            float h11 = v1 ? fmaxf(d1 * acc[mt][nt][3] + bb1, 0.f) : 0.f;
            *(uint2*)&Hs[r0 * 260 + c] = make_uint2(f2tf32(h00), f2tf32(h01));
            *(uint2*)&Hs[r1 * 260 + c] = make_uint2(f2tf32(h10), f2tf32(h11));
        }
    }
    __syncthreads();

    // GEMM2: ts = dinv * (Hs(128x256) @ W2s(256x32))
    {
        int mtile = warpId >> 1;           // 8 m16 tiles
        int nh    = warpId & 1;            // 2 col halves of 16
        float a2c[2][4] = {};
#pragma unroll
        for (int ks = 0; ks < HID1; ks += 8) {
            int rb = mtile * 16;
            unsigned a0 = Hs[(rb + gid    ) * 260 + ks + tg    ];
            unsigned a1 = Hs[(rb + gid + 8) * 260 + ks + tg    ];
            unsigned a2 = Hs[(rb + gid    ) * 260 + ks + tg + 4];
            unsigned a3 = Hs[(rb + gid + 8) * 260 + ks + tg + 4];
#pragma unroll
            for (int nt = 0; nt < 2; nt++) {
                int cb = nh * 16 + nt * 8;
                unsigned b0 = W2s[(ks + tg    ) * 36 + cb + gid];
                unsigned b1v= W2s[(ks + tg + 4) * 36 + cb + gid];
                mma_tf32(a2c[nt], a0, a1, a2, a3, b0, b1v);
            }
        }
        int r0 = tileM + mtile * 16 + gid;
        int r1 = r0 + 8;
        float d0 = (r0 < N_NODES) ? g_dinv[r0] : 0.f;
        float d1 = (r1 < N_NODES) ? g_dinv[r1] : 0.f;
#pragma unroll
        for (int nt = 0; nt < 2; nt++) {
            int c = nh * 16 + nt * 8 + tg * 2;
            if (r0 < N_NODES)
                *(float2*)&g_ts[r0 * HID2 + c] = make_float2(d0 * a2c[nt][0], d0 * a2c[nt][1]);
            if (r1 < N_NODES)
                *(float2*)&g_ts[r1 * HID2 + c] = make_float2(d1 * a2c[nt][2], d1 * a2c[nt][3]);
        }
    }
}

// ---------------- conv2 gather + z ----------------
__global__ void k_agg2(const float* __restrict__ b2) {
    int w = (blockIdx.x * blockDim.x + threadIdx.x) >> 5;
    if (w >= N_NODES) return;
    int lane = threadIdx.x & 31;
    int beg = g_rowptr[w], end = g_rowptr[w + 1];
    float acc = g_ts[w * 32 + lane];
    int j = beg;
    for (; j + 3 < end; j += 4) {
        int s0 = g_csrc[j], s1 = g_csrc[j + 1], s2 = g_csrc[j + 2], s3 = g_csrc[j + 3];
        acc += g_ts[s0 * 32 + lane];
        acc += g_ts[s1 * 32 + lane];
        acc += g_ts[s2 * 32 + lane];
        acc += g_ts[s3 * 32 + lane];
    }
    for (; j < end; j++) acc += g_ts[g_csrc[j] * 32 + lane];
    g_z[w * 32 + lane] = g_dinv[w] * acc + b2[lane];
}

// ---------------- decode: 8 lanes per edge, float4 loads ----------------
__global__ void k_decode(const int* __restrict__ eli, float* __restrict__ out) {
    int t = blockIdx.x * blockDim.x + threadIdx.x;
    int k = t >> 3;
    if (k >= N_LABEL) return;
    int lane = t & 7;
    int a = eli[k];
    int b = eli[N_LABEL + k];
    float4 za = ((const float4*)g_z)[a * 8 + lane];
    float4 zb = ((const float4*)g_z)[b * 8 + lane];
    float p = za.x * zb.x + za.y * zb.y + za.z * zb.z + za.w * zb.w;
    p += __shfl_xor_sync(0xffffffffu, p, 4);
    p += __shfl_xor_sync(0xffffffffu, p, 2);
    p += __shfl_xor_sync(0xffffffffu, p, 1);
    if (lane == 0) out[k] = p;
}

// ---------------- launch ----------------
extern "C" void kernel_launch(void* const* d_in, const int* in_sizes, int n_in,
                              void* d_out, int out_size) {
    const float* x   = (const float*)d_in[0];
    const int*   ei  = (const int*)d_in[1];     // int32 (JAX x64 disabled)
    const int*   eli = (const int*)d_in[2];
    const float* W1  = (const float*)d_in[3];
    const float* b1  = (const float*)d_in[4];
    const float* W2  = (const float*)d_in[5];
    const float* b2  = (const float*)d_in[6];
    float* out = (float*)d_out;
    (void)in_sizes; (void)n_in; (void)out_size;

    cudaFuncSetAttribute(k_gemm12, cudaFuncAttributeMaxDynamicSharedMemorySize,
                         SMEM_WORDS * 4);

    k_zero_cnt<<<(N_NODES + 255) / 256, 256>>>();
    k_hist    <<<(N_EDGES + 255) / 256, 256>>>(ei);
    k_scan_all<<<1, 1024>>>();
    k_fill    <<<(N_EDGES + 255) / 256, 256>>>(ei);

    k_agg1    <<<(N_NODES * 32 + 255) / 256, 256>>>(x);

    k_gemm12  <<<(N_NODES + 127) / 128, 512, SMEM_WORDS * 4>>>(W1, b1, W2);

    k_agg2    <<<(N_NODES * 32 + 255) / 256, 256>>>(b2);
    k_decode  <<<(N_LABEL * 8 + 255) / 256, 256>>>(eli, out);
}

// round 9
// speedup vs baseline: 1.4883x; 1.4883x over previous
#include <cuda_runtime.h>

#define N_NODES 50000
#define N_EDGES 1600000
#define N_LABEL 200000
#define IN_C    128
#define HID1    256
#define HID2    32

#define SCAN_BLK 1024
#define N_SCAN_BLOCKS ((N_NODES + SCAN_BLK - 1) / SCAN_BLK)   // 49

// ---------------- device scratch ----------------
__device__ __align__(256) int   g_cnt   [N_NODES];
__device__ __align__(256) int   g_rowptr[N_NODES + 1];
__device__ __align__(256) int   g_cursor[N_NODES];
__device__ __align__(256) int   g_csrc  [N_EDGES];
__device__ __align__(256) int   g_bsum  [64];
__device__ __align__(256) int   g_boff  [64];
__device__ __align__(256) float g_dinv  [N_NODES];
__device__ __align__(256) float g_S1    [N_NODES * IN_C];
__device__ __align__(256) float g_h1    [N_NODES * HID1];
__device__ __align__(256) float g_ts    [N_NODES * HID2];
__device__ __align__(256) float g_z     [N_NODES * HID2];

// ---------------- tf32 helpers ----------------
__device__ __forceinline__ unsigned f2tf32(float f) {
    unsigned r;
    asm("cvt.rna.tf32.f32 %0, %1;" : "=r"(r) : "f"(f));
    return r;
}
__device__ __forceinline__ void mma_tf32(float* c, unsigned a0, unsigned a1,
                                         unsigned a2, unsigned a3,
                                         unsigned b0, unsigned b1) {
    asm volatile(
        "mma.sync.aligned.m16n8k8.row.col.f32.tf32.tf32.f32 "
        "{%0,%1,%2,%3}, {%4,%5,%6,%7}, {%8,%9}, {%0,%1,%2,%3};"
        : "+f"(c[0]), "+f"(c[1]), "+f"(c[2]), "+f"(c[3])
        : "r"(a0), "r"(a1), "r"(a2), "r"(a3), "r"(b0), "r"(b1));
}

// ---------------- CSR build ----------------
// hist: 4 edges/thread, int4 dst load, fire-and-forget REDs
__global__ void k_hist(const int* __restrict__ ei) {
    int t = blockIdx.x * blockDim.x + threadIdx.x;
    if (t < N_EDGES / 4) {
        int4 d = ((const int4*)(ei + N_EDGES))[t];
        atomicAdd(&g_cnt[d.x], 1);
        atomicAdd(&g_cnt[d.y], 1);
        atomicAdd(&g_cnt[d.z], 1);
        atomicAdd(&g_cnt[d.w], 1);
    }
}

// scan + dinv (cnt final here)
__global__ void k_scan1() {
    __shared__ int sh[SCAN_BLK];
    int i = blockIdx.x * SCAN_BLK + threadIdx.x;
    int v = (i < N_NODES) ? g_cnt[i] : 0;
    if (i < N_NODES) g_dinv[i] = rsqrtf((float)(v + 1));
    sh[threadIdx.x] = v;
    __syncthreads();
#pragma unroll
    for (int off = 1; off < SCAN_BLK; off <<= 1) {
        int t = (threadIdx.x >= off) ? sh[threadIdx.x - off] : 0;
        __syncthreads();
        sh[threadIdx.x] += t;
        __syncthreads();
    }
    if (i < N_NODES) g_rowptr[i] = sh[threadIdx.x] - v;
    if (threadIdx.x == SCAN_BLK - 1) g_bsum[blockIdx.x] = sh[SCAN_BLK - 1];
}

__global__ void k_scan2() {
    __shared__ int sh[64];
    int v = (threadIdx.x < N_SCAN_BLOCKS) ? g_bsum[threadIdx.x] : 0;
    sh[threadIdx.x] = v;
    __syncthreads();
#pragma unroll
    for (int off = 1; off < 64; off <<= 1) {
        int t = (threadIdx.x >= off) ? sh[threadIdx.x - off] : 0;
        __syncthreads();
        sh[threadIdx.x] += t;
        __syncthreads();
    }
    g_boff[threadIdx.x] = sh[threadIdx.x] - v;
}

__global__ void k_scan3() {
    int i = blockIdx.x * blockDim.x + threadIdx.x;
    if (i < N_NODES) {
        int r = g_rowptr[i] + g_boff[i >> 10];
        g_rowptr[i] = r;
        g_cursor[i] = r;
    }
    if (i == 0) g_rowptr[N_NODES] = N_EDGES;
}

// fill: 4 edges/thread — 4 independent atomic round-trips in flight
__global__ void k_fill(const int* __restrict__ ei) {
    int t = blockIdx.x * blockDim.x + threadIdx.x;
    if (t < N_EDGES / 4) {
        int4 s = ((const int4*)ei)[t];
        int4 d = ((const int4*)(ei + N_EDGES))[t];
        int p0 = atomicAdd(&g_cursor[d.x], 1);
        int p1 = atomicAdd(&g_cursor[d.y], 1);
        int p2 = atomicAdd(&g_cursor[d.z], 1);
        int p3 = atomicAdd(&g_cursor[d.w], 1);
        g_csrc[p0] = s.x;
        g_csrc[p1] = s.y;
        g_csrc[p2] = s.z;
        g_csrc[p3] = s.w;
    }
}

// ---------------- conv1 gather: S1[i] = dinv[i]*x[i] + sum dinv[src]*x[src]
__global__ void k_agg1(const float* __restrict__ x) {
    int w = (blockIdx.x * blockDim.x + threadIdx.x) >> 5;
    if (w >= N_NODES) return;
    int lane = threadIdx.x & 31;
    int beg = g_rowptr[w], end = g_rowptr[w + 1];
    const float4* xv = (const float4*)x;

    float dw = g_dinv[w];
    float4 s = xv[w * 32 + lane];
    float4 acc = make_float4(dw * s.x, dw * s.y, dw * s.z, dw * s.w);

    int j = beg;
    for (; j + 3 < end; j += 4) {
        int s0 = g_csrc[j], s1 = g_csrc[j + 1], s2 = g_csrc[j + 2], s3 = g_csrc[j + 3];
        float d0 = g_dinv[s0], d1 = g_dinv[s1], d2 = g_dinv[s2], d3 = g_dinv[s3];
        float4 v0 = xv[s0 * 32 + lane];
        float4 v1 = xv[s1 * 32 + lane];
        float4 v2 = xv[s2 * 32 + lane];
        float4 v3 = xv[s3 * 32 + lane];
        acc.x += d0*v0.x; acc.y += d0*v0.y; acc.z += d0*v0.z; acc.w += d0*v0.w;
        acc.x += d1*v1.x; acc.y += d1*v1.y; acc.z += d1*v1.z; acc.w += d1*v1.w;
        acc.x += d2*v2.x; acc.y += d2*v2.y; acc.z += d2*v2.z; acc.w += d2*v2.w;
        acc.x += d3*v3.x; acc.y += d3*v3.y; acc.z += d3*v3.z; acc.w += d3*v3.w;
    }
    for (; j < end; j++) {
        int sj = g_csrc[j];
        float dj = g_dinv[sj];
        float4 v = xv[sj * 32 + lane];
        acc.x += dj*v.x; acc.y += dj*v.y; acc.z += dj*v.z; acc.w += dj*v.w;
    }
    ((float4*)g_S1)[w * 32 + lane] = acc;
}

// ---------------- GEMM1 (tf32 MMA): h1 = relu(dinv*(S1@W1)+b1)  [50000x128]x[128x256]
// 8 warps (4M x 2N); BM=128 BN=64 BK=32; warp = 32x32 (2 m16 x 4 n8)
#define G1_AS 36
#define G1_BS 72
__global__ void k_gemm1(const float* __restrict__ W, const float* __restrict__ b1) {
    __shared__ unsigned As[128 * G1_AS];
    __shared__ unsigned Bs[32 * G1_BS];
    const int tid   = threadIdx.x;
    const int tileM = blockIdx.x * 128;
    const int tileN = blockIdx.y * 64;
    const int warpId = tid >> 5, lane = tid & 31;
    const int warpM = warpId & 3, warpN = warpId >> 2;
    const int gid = lane >> 2, tg = lane & 3;

    float acc[2][4][4] = {};

    for (int k0 = 0; k0 < IN_C; k0 += 32) {
#pragma unroll
        for (int i = 0; i < 4; i++) {
            int idx = tid + i * 256;
            int r   = idx >> 3;
            int c0  = (idx & 7) * 4;
            int grow = tileM + r;
            float4 v = make_float4(0.f,0.f,0.f,0.f);
            if (grow < N_NODES) v = *(const float4*)&g_S1[grow * IN_C + k0 + c0];
            unsigned* a = &As[r * G1_AS + c0];
            a[0]=f2tf32(v.x); a[1]=f2tf32(v.y); a[2]=f2tf32(v.z); a[3]=f2tf32(v.w);
        }
#pragma unroll
        for (int i = 0; i < 2; i++) {
            int idx = tid + i * 256;
            int r   = idx >> 4;
            int c   = (idx & 15) * 4;
            float4 v = *(const float4*)&W[(k0 + r) * HID1 + tileN + c];
            unsigned* b = &Bs[r * G1_BS + c];
            b[0]=f2tf32(v.x); b[1]=f2tf32(v.y); b[2]=f2tf32(v.z); b[3]=f2tf32(v.w);
        }
        __syncthreads();
#pragma unroll
        for (int ks = 0; ks < 32; ks += 8) {
            unsigned a[2][4];
#pragma unroll
            for (int mt = 0; mt < 2; mt++) {
                int rb = warpM * 32 + mt * 16;
                a[mt][0] = As[(rb + gid    ) * G1_AS + ks + tg    ];
                a[mt][1] = As[(rb + gid + 8) * G1_AS + ks + tg    ];
                a[mt][2] = As[(rb + gid    ) * G1_AS + ks + tg + 4];
                a[mt][3] = As[(rb + gid + 8) * G1_AS + ks + tg + 4];
            }
#pragma unroll
            for (int nt = 0; nt < 4; nt++) {
                int cb = warpN * 32 + nt * 8;
                unsigned b0 = Bs[(ks + tg    ) * G1_BS + cb + gid];
                unsigned b1v= Bs[(ks + tg + 4) * G1_BS + cb + gid];
#pragma unroll
                for (int mt = 0; mt < 2; mt++)
                    mma_tf32(acc[mt][nt], a[mt][0], a[mt][1], a[mt][2], a[mt][3], b0, b1v);
            }
        }
        __syncthreads();
    }

#pragma unroll
    for (int mt = 0; mt < 2; mt++) {
        int r0 = tileM + warpM * 32 + mt * 16 + gid;
        int r1 = r0 + 8;
        float d0 = (r0 < N_NODES) ? g_dinv[r0] : 0.f;
        float d1 = (r1 < N_NODES) ? g_dinv[r1] : 0.f;
#pragma unroll
        for (int nt = 0; nt < 4; nt++) {
            int c = tileN + warpN * 32 + nt * 8 + tg * 2;
            float bb0 = b1[c], bb1 = b1[c + 1];
            if (r0 < N_NODES) {
                float2 o;
                o.x = fmaxf(d0 * acc[mt][nt][0] + bb0, 0.f);
                o.y = fmaxf(d0 * acc[mt][nt][1] + bb1, 0.f);
                *(float2*)&g_h1[r0 * HID1 + c] = o;
            }
            if (r1 < N_NODES) {
                float2 o;
                o.x = fmaxf(d1 * acc[mt][nt][2] + bb0, 0.f);
                o.y = fmaxf(d1 * acc[mt][nt][3] + bb1, 0.f);
                *(float2*)&g_h1[r1 * HID1 + c] = o;
            }
        }
    }
}

// ---------------- GEMM2 (tf32 MMA): ts = dinv*(h1@W2)  [50000x256]x[256x32]
#define G2_AS 36
#define G2_BS 72
__global__ void k_gemm2(const float* __restrict__ W2) {
    __shared__ unsigned As[128 * G2_AS];
    __shared__ unsigned Bs[32 * G2_BS];
    const int tid   = threadIdx.x;
    const int tileM = blockIdx.x * 128;
    const int warpId = tid >> 5, lane = tid & 31;
    const int gid = lane >> 2, tg = lane & 3;

    float acc[4][4] = {};

    for (int k0 = 0; k0 < HID1; k0 += 32) {
#pragma unroll
        for (int i = 0; i < 4; i++) {
            int idx = tid + i * 256;
            int r   = idx >> 3;
            int c0  = (idx & 7) * 4;
            int grow = tileM + r;
            float4 v = make_float4(0.f,0.f,0.f,0.f);
            if (grow < N_NODES) v = *(const float4*)&g_h1[grow * HID1 + k0 + c0];
            unsigned* a = &As[r * G2_AS + c0];
            a[0]=f2tf32(v.x); a[1]=f2tf32(v.y); a[2]=f2tf32(v.z); a[3]=f2tf32(v.w);
        }
        {
            int r = tid >> 3;
            int c = (tid & 7) * 4;
            float4 v = *(const float4*)&W2[(k0 + r) * HID2 + c];
            unsigned* b = &Bs[r * G2_BS + c];
            b[0]=f2tf32(v.x); b[1]=f2tf32(v.y); b[2]=f2tf32(v.z); b[3]=f2tf32(v.w);
        }
        __syncthreads();
#pragma unroll
        for (int ks = 0; ks < 32; ks += 8) {
            int rb = warpId * 16;
            unsigned a0 = As[(rb + gid    ) * G2_AS + ks + tg    ];
            unsigned a1 = As[(rb + gid + 8) * G2_AS + ks + tg    ];
            unsigned a2 = As[(rb + gid    ) * G2_AS + ks + tg + 4];
            unsigned a3 = As[(rb + gid + 8) * G2_AS + ks + tg + 4];
#pragma unroll
            for (int nt = 0; nt < 4; nt++) {
                int cb = nt * 8;
                unsigned b0 = Bs[(ks + tg    ) * G2_BS + cb + gid];
                unsigned b1v= Bs[(ks + tg + 4) * G2_BS + cb + gid];
                mma_tf32(acc[nt], a0, a1, a2, a3, b0, b1v);
            }
        }
        __syncthreads();
    }

    int r0 = tileM + warpId * 16 + gid;
    int r1 = r0 + 8;
    float d0 = (r0 < N_NODES) ? g_dinv[r0] : 0.f;
    float d1 = (r1 < N_NODES) ? g_dinv[r1] : 0.f;
#pragma unroll
    for (int nt = 0; nt < 4; nt++) {
        int c = nt * 8 + tg * 2;
        if (r0 < N_NODES) {
            float2 o = make_float2(d0 * acc[nt][0], d0 * acc[nt][1]);
            *(float2*)&g_ts[r0 * HID2 + c] = o;
        }
        if (r1 < N_NODES) {
            float2 o = make_float2(d1 * acc[nt][2], d1 * acc[nt][3]);
            *(float2*)&g_ts[r1 * HID2 + c] = o;
        }
    }
}

// ---------------- conv2 gather + z ----------------
__global__ void k_agg2(const float* __restrict__ b2) {
    int w = (blockIdx.x * blockDim.x + threadIdx.x) >> 5;
    if (w >= N_NODES) return;
    int lane = threadIdx.x & 31;
    int beg = g_rowptr[w], end = g_rowptr[w + 1];
    float acc = g_ts[w * 32 + lane];
    int j = beg;
    for (; j + 3 < end; j += 4) {
        int s0 = g_csrc[j], s1 = g_csrc[j + 1], s2 = g_csrc[j + 2], s3 = g_csrc[j + 3];
        acc += g_ts[s0 * 32 + lane];
        acc += g_ts[s1 * 32 + lane];
        acc += g_ts[s2 * 32 + lane];
        acc += g_ts[s3 * 32 + lane];
    }
    for (; j < end; j++) acc += g_ts[g_csrc[j] * 32 + lane];
    g_z[w * 32 + lane] = g_dinv[w] * acc + b2[lane];
}

// ---------------- decode: 8 lanes per edge, float4 loads ----------------
__global__ void k_decode(const int* __restrict__ eli, float* __restrict__ out) {
    int t = blockIdx.x * blockDim.x + threadIdx.x;
    int k = t >> 3;
    if (k >= N_LABEL) return;
    int lane = t & 7;
    int a = eli[k];
    int b = eli[N_LABEL + k];
    float4 za = ((const float4*)g_z)[a * 8 + lane];
    float4 zb = ((const float4*)g_z)[b * 8 + lane];
    float p = za.x * zb.x + za.y * zb.y + za.z * zb.z + za.w * zb.w;
    p += __shfl_xor_sync(0xffffffffu, p, 4);
    p += __shfl_xor_sync(0xffffffffu, p, 2);
    p += __shfl_xor_sync(0xffffffffu, p, 1);
    if (lane == 0) out[k] = p;
}

// ---------------- launch ----------------
extern "C" void kernel_launch(void* const* d_in, const int* in_sizes, int n_in,
                              void* d_out, int out_size) {
    const float* x   = (const float*)d_in[0];
    const int*   ei  = (const int*)d_in[1];     // int32 (JAX x64 disabled)
    const int*   eli = (const int*)d_in[2];
    const float* W1  = (const float*)d_in[3];
    const float* b1  = (const float*)d_in[4];
    const float* W2  = (const float*)d_in[5];
    const float* b2  = (const float*)d_in[6];
    float* out = (float*)d_out;
    (void)in_sizes; (void)n_in; (void)out_size;

    void* cnt_ptr = nullptr;
    cudaGetSymbolAddress(&cnt_ptr, g_cnt);
    cudaMemsetAsync(cnt_ptr, 0, N_NODES * sizeof(int));

    k_hist    <<<(N_EDGES / 4 + 255) / 256, 256>>>(ei);
    k_scan1   <<<N_SCAN_BLOCKS, SCAN_BLK>>>();
    k_scan2   <<<1, 64>>>();
    k_scan3   <<<(N_NODES + 255) / 256, 256>>>();
    k_fill    <<<(N_EDGES / 4 + 255) / 256, 256>>>(ei);

    k_agg1    <<<(N_NODES * 32 + 255) / 256, 256>>>(x);

    dim3 g1((N_NODES + 127) / 128, HID1 / 64);
    k_gemm1   <<<g1, 256>>>(W1, b1);
    k_gemm2   <<<(N_NODES + 127) / 128, 256>>>(W2);

    k_agg2    <<<(N_NODES * 32 + 255) / 256, 256>>>(b2);
    k_decode  <<<(N_LABEL * 8 + 255) / 256, 256>>>(eli, out);
}

// round 10
// speedup vs baseline: 1.5782x; 1.0604x over previous
#include <cuda_runtime.h>
#include <cuda_fp16.h>

#define N_NODES 50000
#define N_EDGES 1600000
#define N_LABEL 200000
#define IN_C    128
#define HID1    256
#define HID2    32

#define SCAN_BLK 1024
#define N_SCAN_BLOCKS ((N_NODES + SCAN_BLK - 1) / SCAN_BLK)   // 49
#define PACK_BLOCKS   (N_NODES * 32 / 256)                     // 6250
#define FILL_BLOCKS   ((N_EDGES / 4 + 255) / 256)              // 1563

// ---------------- device scratch ----------------
__device__ __align__(256) int    g_cnt   [N_NODES];
__device__ __align__(256) int    g_rowptr[N_NODES + 1];
__device__ __align__(256) int    g_cursor[N_NODES];
__device__ __align__(256) int    g_csrc  [N_EDGES];
__device__ __align__(256) int    g_bsum  [64];
__device__            int        g_scan_done;
__device__ __align__(256) float  g_dinv  [N_NODES];
__device__ __align__(256) __half g_xh    [N_NODES * IN_C];   // fp16 dinv*x
__device__ __align__(256) float  g_S1    [N_NODES * IN_C];
__device__ __align__(256) float  g_h1    [N_NODES * HID1];
__device__ __align__(256) float  g_ts    [N_NODES * HID2];
__device__ __align__(256) float  g_z     [N_NODES * HID2];

// ---------------- tf32 helpers ----------------
__device__ __forceinline__ unsigned f2tf32(float f) {
    unsigned r;
    asm("cvt.rna.tf32.f32 %0, %1;" : "=r"(r) : "f"(f));
    return r;
}
__device__ __forceinline__ void mma_tf32(float* c, unsigned a0, unsigned a1,
                                         unsigned a2, unsigned a3,
                                         unsigned b0, unsigned b1) {
    asm volatile(
        "mma.sync.aligned.m16n8k8.row.col.f32.tf32.tf32.f32 "
        "{%0,%1,%2,%3}, {%4,%5,%6,%7}, {%8,%9}, {%0,%1,%2,%3};"
        : "+f"(c[0]), "+f"(c[1]), "+f"(c[2]), "+f"(c[3])
        : "r"(a0), "r"(a1), "r"(a2), "r"(a3), "r"(b0), "r"(b1));
}

// ---------------- hist: 4 edges/thread (also resets scan barrier) ----------------
__global__ void k_hist(const int* __restrict__ ei) {
    if (blockIdx.x == 0 && threadIdx.x == 0) g_scan_done = 0;
    int t = blockIdx.x * blockDim.x + threadIdx.x;
    if (t < N_EDGES / 4) {
        int4 d = ((const int4*)(ei + N_EDGES))[t];
        atomicAdd(&g_cnt[d.x], 1);
        atomicAdd(&g_cnt[d.y], 1);
        atomicAdd(&g_cnt[d.z], 1);
        atomicAdd(&g_cnt[d.w], 1);
    }
}

// ---------------- fused scan: 49 co-resident blocks + spin grid-barrier ----------------
__global__ void k_scan() {
    __shared__ int sh[SCAN_BLK];
    __shared__ int sh2[64];
    const int b = blockIdx.x, t = threadIdx.x;
    int i = b * SCAN_BLK + t;
    int v = (i < N_NODES) ? g_cnt[i] : 0;
    if (i < N_NODES) g_dinv[i] = rsqrtf((float)(v + 1));
    sh[t] = v;
    __syncthreads();
#pragma unroll
    for (int off = 1; off < SCAN_BLK; off <<= 1) {
        int tmp = (t >= off) ? sh[t - off] : 0;
        __syncthreads();
        sh[t] += tmp;
        __syncthreads();
    }
    int incl = sh[t];
    if (t == SCAN_BLK - 1) {
        g_bsum[b] = incl;
        __threadfence();
        atomicAdd(&g_scan_done, 1);
    }
    if (t == 0) {
        while (*(volatile int*)&g_scan_done < (int)gridDim.x) {}
    }
    __syncthreads();
    __threadfence();
    // 64-wide scan of block sums (redundant per block, cheap)
    if (t < 64) sh2[t] = (t < (int)gridDim.x) ? *(volatile int*)&g_bsum[t] : 0;
    __syncthreads();
#pragma unroll
    for (int off = 1; off < 64; off <<= 1) {
        int tmp = (t >= off && t < 64) ? sh2[t - off] : 0;
        __syncthreads();
        if (t < 64) sh2[t] += tmp;
        __syncthreads();
    }
    int boff = (b > 0) ? sh2[b - 1] : 0;
    if (i < N_NODES) {
        int r = boff + incl - v;
        g_rowptr[i] = r;
        g_cursor[i] = r;
    }
    if (b == 0 && t == 0) g_rowptr[N_NODES] = N_EDGES;
}

// ---------------- fused pack (xh = fp16(dinv*x)) + fill (CSR columns) ----------------
__global__ void k_packfill(const float* __restrict__ x, const int* __restrict__ ei) {
    int bi = blockIdx.x;
    if (bi < PACK_BLOCKS) {
        int t = bi * 256 + threadIdx.x;        // over N_NODES*32 float4 lanes
        int node = t >> 5;
        float di = g_dinv[node];
        float4 v = ((const float4*)x)[t];
        union { __half2 h[2]; uint2 u; } cv;
        cv.h[0] = __floats2half2_rn(di * v.x, di * v.y);
        cv.h[1] = __floats2half2_rn(di * v.z, di * v.w);
        ((uint2*)g_xh)[t] = cv.u;
    } else {
        int t = (bi - PACK_BLOCKS) * 256 + threadIdx.x;
        if (t < N_EDGES / 4) {
            int4 s = ((const int4*)ei)[t];
            int4 d = ((const int4*)(ei + N_EDGES))[t];
            int p0 = atomicAdd(&g_cursor[d.x], 1);
            int p1 = atomicAdd(&g_cursor[d.y], 1);
            int p2 = atomicAdd(&g_cursor[d.z], 1);
            int p3 = atomicAdd(&g_cursor[d.w], 1);
            g_csrc[p0] = s.x;
            g_csrc[p1] = s.y;
            g_csrc[p2] = s.z;
            g_csrc[p3] = s.w;
        }
    }
}

// ---------------- conv1 gather (fp16 rows, fp32 accum): S1[i] = sum xh rows ----------------
__global__ void k_agg1() {
    int w = (blockIdx.x * blockDim.x + threadIdx.x) >> 5;
    if (w >= N_NODES) return;
    int lane = threadIdx.x & 31;
    int beg = g_rowptr[w], end = g_rowptr[w + 1];
    const uint2* xv = (const uint2*)g_xh;     // 4 halves per lane

    float4 acc = make_float4(0.f, 0.f, 0.f, 0.f);
    {   // self loop
        uint2 u = xv[w * 32 + lane];
        float2 f0 = __half22float2(*(__half2*)&u.x);
        float2 f1 = __half22float2(*(__half2*)&u.y);
        acc.x = f0.x; acc.y = f0.y; acc.z = f1.x; acc.w = f1.y;
    }
    int j = beg;
    for (; j + 3 < end; j += 4) {
        int s0 = g_csrc[j], s1 = g_csrc[j + 1], s2 = g_csrc[j + 2], s3 = g_csrc[j + 3];
        uint2 u0 = xv[s0 * 32 + lane];
        uint2 u1 = xv[s1 * 32 + lane];
        uint2 u2 = xv[s2 * 32 + lane];
        uint2 u3 = xv[s3 * 32 + lane];
        float2 a0 = __half22float2(*(__half2*)&u0.x), b0 = __half22float2(*(__half2*)&u0.y);
        float2 a1 = __half22float2(*(__half2*)&u1.x), b1 = __half22float2(*(__half2*)&u1.y);
        float2 a2 = __half22float2(*(__half2*)&u2.x), b2 = __half22float2(*(__half2*)&u2.y);
        float2 a3 = __half22float2(*(__half2*)&u3.x), b3 = __half22float2(*(__half2*)&u3.y);
        acc.x += a0.x + a1.x + a2.x + a3.x;
        acc.y += a0.y + a1.y + a2.y + a3.y;
        acc.z += b0.x + b1.x + b2.x + b3.x;
        acc.w += b0.y + b1.y + b2.y + b3.y;
    }
    for (; j < end; j++) {
        uint2 u = xv[g_csrc[j] * 32 + lane];
        float2 f0 = __half22float2(*(__half2*)&u.x);
        float2 f1 = __half22float2(*(__half2*)&u.y);
        acc.x += f0.x; acc.y += f0.y; acc.z += f1.x; acc.w += f1.y;
    }
    ((float4*)g_S1)[w * 32 + lane] = acc;
}

// ---------------- GEMM1 (tf32 MMA): h1 = relu(dinv*(S1@W1)+b1)  [50000x128]x[128x256]
#define G1_AS 36
#define G1_BS 72
__global__ void k_gemm1(const float* __restrict__ W, const float* __restrict__ b1) {
    __shared__ unsigned As[128 * G1_AS];
    __shared__ unsigned Bs[32 * G1_BS];
    const int tid   = threadIdx.x;
    const int tileM = blockIdx.x * 128;
    const int tileN = blockIdx.y * 64;
    const int warpId = tid >> 5, lane = tid & 31;
    const int warpM = warpId & 3, warpN = warpId >> 2;
    const int gid = lane >> 2, tg = lane & 3;

    float acc[2][4][4] = {};

    for (int k0 = 0; k0 < IN_C; k0 += 32) {
#pragma unroll
        for (int i = 0; i < 4; i++) {
            int idx = tid + i * 256;
            int r   = idx >> 3;
            int c0  = (idx & 7) * 4;
            int grow = tileM + r;
            float4 v = make_float4(0.f,0.f,0.f,0.f);
            if (grow < N_NODES) v = *(const float4*)&g_S1[grow * IN_C + k0 + c0];
            unsigned* a = &As[r * G1_AS + c0];
            a[0]=f2tf32(v.x); a[1]=f2tf32(v.y); a[2]=f2tf32(v.z); a[3]=f2tf32(v.w);
        }
#pragma unroll
        for (int i = 0; i < 2; i++) {
            int idx = tid + i * 256;
            int r   = idx >> 4;
            int c   = (idx & 15) * 4;
            float4 v = *(const float4*)&W[(k0 + r) * HID1 + tileN + c];
            unsigned* b = &Bs[r * G1_BS + c];
            b[0]=f2tf32(v.x); b[1]=f2tf32(v.y); b[2]=f2tf32(v.z); b[3]=f2tf32(v.w);
        }
        __syncthreads();
#pragma unroll
        for (int ks = 0; ks < 32; ks += 8) {
            unsigned a[2][4];
#pragma unroll
            for (int mt = 0; mt < 2; mt++) {
                int rb = warpM * 32 + mt * 16;
                a[mt][0] = As[(rb + gid    ) * G1_AS + ks + tg    ];
                a[mt][1] = As[(rb + gid + 8) * G1_AS + ks + tg    ];
                a[mt][2] = As[(rb + gid    ) * G1_AS + ks + tg + 4];
                a[mt][3] = As[(rb + gid + 8) * G1_AS + ks + tg + 4];
            }
#pragma unroll
            for (int nt = 0; nt < 4; nt++) {
                int cb = warpN * 32 + nt * 8;
                unsigned b0 = Bs[(ks + tg    ) * G1_BS + cb + gid];
                unsigned b1v= Bs[(ks + tg + 4) * G1_BS + cb + gid];
#pragma unroll
                for (int mt = 0; mt < 2; mt++)
                    mma_tf32(acc[mt][nt], a[mt][0], a[mt][1], a[mt][2], a[mt][3], b0, b1v);
            }
        }
        __syncthreads();
    }

#pragma unroll
    for (int mt = 0; mt < 2; mt++) {
        int r0 = tileM + warpM * 32 + mt * 16 + gid;
        int r1 = r0 + 8;
        float d0 = (r0 < N_NODES) ? g_dinv[r0] : 0.f;
        float d1 = (r1 < N_NODES) ? g_dinv[r1] : 0.f;
#pragma unroll
        for (int nt = 0; nt < 4; nt++) {
            int c = tileN + warpN * 32 + nt * 8 + tg * 2;
            float bb0 = b1[c], bb1 = b1[c + 1];
            if (r0 < N_NODES) {
                float2 o;
                o.x = fmaxf(d0 * acc[mt][nt][0] + bb0, 0.f);
                o.y = fmaxf(d0 * acc[mt][nt][1] + bb1, 0.f);
                *(float2*)&g_h1[r0 * HID1 + c] = o;
            }
            if (r1 < N_NODES) {
                float2 o;
                o.x = fmaxf(d1 * acc[mt][nt][2] + bb0, 0.f);
                o.y = fmaxf(d1 * acc[mt][nt][3] + bb1, 0.f);
                *(float2*)&g_h1[r1 * HID1 + c] = o;
            }
        }
    }
}

// ---------------- GEMM2 (tf32 MMA): ts = dinv*(h1@W2)  [50000x256]x[256x32]
#define G2_AS 36
#define G2_BS 72
__global__ void k_gemm2(const float* __restrict__ W2) {
    __shared__ unsigned As[128 * G2_AS];
    __shared__ unsigned Bs[32 * G2_BS];
    const int tid   = threadIdx.x;
    const int tileM = blockIdx.x * 128;
    const int warpId = tid >> 5, lane = tid & 31;
    const int gid = lane >> 2, tg = lane & 3;

    float acc[4][4] = {};

    for (int k0 = 0; k0 < HID1; k0 += 32) {
#pragma unroll
        for (int i = 0; i < 4; i++) {
            int idx = tid + i * 256;
            int r   = idx >> 3;
            int c0  = (idx & 7) * 4;
            int grow = tileM + r;
            float4 v = make_float4(0.f,0.f,0.f,0.f);
            if (grow < N_NODES) v = *(const float4*)&g_h1[grow * HID1 + k0 + c0];
            unsigned* a = &As[r * G2_AS + c0];
            a[0]=f2tf32(v.x); a[1]=f2tf32(v.y); a[2]=f2tf32(v.z); a[3]=f2tf32(v.w);
        }
        {
            int r = tid >> 3;
            int c = (tid & 7) * 4;
            float4 v = *(const float4*)&W2[(k0 + r) * HID2 + c];
            unsigned* b = &Bs[r * G2_BS + c];
            b[0]=f2tf32(v.x); b[1]=f2tf32(v.y); b[2]=f2tf32(v.z); b[3]=f2tf32(v.w);
        }
        __syncthreads();
#pragma unroll
        for (int ks = 0; ks < 32; ks += 8) {
            int rb = warpId * 16;
            unsigned a0 = As[(rb + gid    ) * G2_AS + ks + tg    ];
            unsigned a1 = As[(rb + gid + 8) * G2_AS + ks + tg    ];
            unsigned a2 = As[(rb + gid    ) * G2_AS + ks + tg + 4];
            unsigned a3 = As[(rb + gid + 8) * G2_AS + ks + tg + 4];
#pragma unroll
            for (int nt = 0; nt < 4; nt++) {
                int cb = nt * 8;
                unsigned b0 = Bs[(ks + tg    ) * G2_BS + cb + gid];
                unsigned b1v= Bs[(ks + tg + 4) * G2_BS + cb + gid];
                mma_tf32(acc[nt], a0, a1, a2, a3, b0, b1v);
            }
        }
        __syncthreads();
    }

    int r0 = tileM + warpId * 16 + gid;
    int r1 = r0 + 8;
    float d0 = (r0 < N_NODES) ? g_dinv[r0] : 0.f;
    float d1 = (r1 < N_NODES) ? g_dinv[r1] : 0.f;
#pragma unroll
    for (int nt = 0; nt < 4; nt++) {
        int c = nt * 8 + tg * 2;
        if (r0 < N_NODES) {
            float2 o = make_float2(d0 * acc[nt][0], d0 * acc[nt][1]);
            *(float2*)&g_ts[r0 * HID2 + c] = o;
        }
        if (r1 < N_NODES) {
            float2 o = make_float2(d1 * acc[nt][2], d1 * acc[nt][3]);
            *(float2*)&g_ts[r1 * HID2 + c] = o;
        }
    }
}

// ---------------- conv2 gather + z (fp32) ----------------
__global__ void k_agg2(const float* __restrict__ b2) {
    int w = (blockIdx.x * blockDim.x + threadIdx.x) >> 5;
    if (w >= N_NODES) return;
    int lane = threadIdx.x & 31;
    int beg = g_rowptr[w], end = g_rowptr[w + 1];
    float acc = g_ts[w * 32 + lane];
    int j = beg;
    for (; j + 3 < end; j += 4) {
        int s0 = g_csrc[j], s1 = g_csrc[j + 1], s2 = g_csrc[j + 2], s3 = g_csrc[j + 3];
        acc += g_ts[s0 * 32 + lane];
        acc += g_ts[s1 * 32 + lane];
        acc += g_ts[s2 * 32 + lane];
        acc += g_ts[s3 * 32 + lane];
    }
    for (; j < end; j++) acc += g_ts[g_csrc[j] * 32 + lane];
    g_z[w * 32 + lane] = g_dinv[w] * acc + b2[lane];
}

// ---------------- decode: 8 lanes per edge, float4 loads ----------------
__global__ void k_decode(const int* __restrict__ eli, float* __restrict__ out) {
    int t = blockIdx.x * blockDim.x + threadIdx.x;
    int k = t >> 3;
    if (k >= N_LABEL) return;
    int lane = t & 7;
    int a = eli[k];
    int b = eli[N_LABEL + k];
    float4 za = ((const float4*)g_z)[a * 8 + lane];
    float4 zb = ((const float4*)g_z)[b * 8 + lane];
    float p = za.x * zb.x + za.y * zb.y + za.z * zb.z + za.w * zb.w;
    p += __shfl_xor_sync(0xffffffffu, p, 4);
    p += __shfl_xor_sync(0xffffffffu, p, 2);
    p += __shfl_xor_sync(0xffffffffu, p, 1);
    if (lane == 0) out[k] = p;
}

// ---------------- launch ----------------
extern "C" void kernel_launch(void* const* d_in, const int* in_sizes, int n_in,
                              void* d_out, int out_size) {
    const float* x   = (const float*)d_in[0];
    const int*   ei  = (const int*)d_in[1];     // int32 (JAX x64 disabled)
    const int*   eli = (const int*)d_in[2];
    const float* W1  = (const float*)d_in[3];
    const float* b1  = (const float*)d_in[4];
    const float* W2  = (const float*)d_in[5];
    const float* b2  = (const float*)d_in[6];
    float* out = (float*)d_out;
    (void)in_sizes; (void)n_in; (void)out_size;

    void* cnt_ptr = nullptr;
    cudaGetSymbolAddress(&cnt_ptr, g_cnt);
    cudaMemsetAsync(cnt_ptr, 0, N_NODES * sizeof(int));

    k_hist    <<<(N_EDGES / 4 + 255) / 256, 256>>>(ei);
    k_scan    <<<N_SCAN_BLOCKS, SCAN_BLK>>>();
    k_packfill<<<PACK_BLOCKS + FILL_BLOCKS, 256>>>(x, ei);

    k_agg1    <<<(N_NODES * 32 + 255) / 256, 256>>>();

    dim3 g1((N_NODES + 127) / 128, HID1 / 64);
    k_gemm1   <<<g1, 256>>>(W1, b1);
    k_gemm2   <<<(N_NODES + 127) / 128, 256>>>(W2);

    k_agg2    <<<(N_NODES * 32 + 255) / 256, 256>>>(b2);
    k_decode  <<<(N_LABEL * 8 + 255) / 256, 256>>>(eli, out);
}

// round 11
// speedup vs baseline: 1.6964x; 1.0749x over previous
#include <cuda_runtime.h>
#include <cuda_fp16.h>

#define N_NODES 50000
#define N_EDGES 1600000
#define N_LABEL 200000
#define IN_C    128
#define HID1    256
#define HID2    32

#define SCAN_BLK 1024
#define N_SCAN_BLOCKS ((N_NODES + SCAN_BLK - 1) / SCAN_BLK)   // 49
#define PACK_BLOCKS   (N_NODES * 32 / 256)                     // 6250
#define FILL_BLOCKS   ((N_EDGES / 4 + 255) / 256)              // 1563

// ---------------- device scratch ----------------
__device__ __align__(256) int    g_cnt   [N_NODES];
__device__ __align__(256) int    g_rowptr[N_NODES + 1];
__device__ __align__(256) int    g_cursor[N_NODES];
__device__ __align__(256) int    g_csrc  [N_EDGES];
__device__ __align__(256) int    g_bsum  [64];
__device__            int        g_scan_done;
__device__ __align__(256) float  g_dinv  [N_NODES];
__device__ __align__(256) __half g_xh    [N_NODES * IN_C];   // fp16 dinv*x
__device__ __align__(256) float  g_S1    [N_NODES * IN_C];
__device__ __align__(256) float  g_h1    [N_NODES * HID1];
__device__ __align__(256) __half g_th    [N_NODES * HID2];   // fp16 dinv*(h1@W2)
__device__ __align__(256) float  g_z     [N_NODES * HID2];

// ---------------- tf32 helpers ----------------
__device__ __forceinline__ unsigned f2tf32(float f) {
    unsigned r;
    asm("cvt.rna.tf32.f32 %0, %1;" : "=r"(r) : "f"(f));
    return r;
}
__device__ __forceinline__ void mma_tf32(float* c, unsigned a0, unsigned a1,
                                         unsigned a2, unsigned a3,
                                         unsigned b0, unsigned b1) {
    asm volatile(
        "mma.sync.aligned.m16n8k8.row.col.f32.tf32.tf32.f32 "
        "{%0,%1,%2,%3}, {%4,%5,%6,%7}, {%8,%9}, {%0,%1,%2,%3};"
        : "+f"(c[0]), "+f"(c[1]), "+f"(c[2]), "+f"(c[3])
        : "r"(a0), "r"(a1), "r"(a2), "r"(a3), "r"(b0), "r"(b1));
}

// ---------------- hist: 4 edges/thread (also resets scan barrier) ----------------
__global__ void k_hist(const int* __restrict__ ei) {
    if (blockIdx.x == 0 && threadIdx.x == 0) g_scan_done = 0;
    int t = blockIdx.x * blockDim.x + threadIdx.x;
    if (t < N_EDGES / 4) {
        int4 d = ((const int4*)(ei + N_EDGES))[t];
        atomicAdd(&g_cnt[d.x], 1);
        atomicAdd(&g_cnt[d.y], 1);
        atomicAdd(&g_cnt[d.z], 1);
        atomicAdd(&g_cnt[d.w], 1);
    }
}

// ---------------- fused scan: 49 co-resident blocks + spin grid-barrier ----------------
__global__ void k_scan() {
    __shared__ int sh[SCAN_BLK];
    __shared__ int sh2[64];
    const int b = blockIdx.x, t = threadIdx.x;
    int i = b * SCAN_BLK + t;
    int v = (i < N_NODES) ? g_cnt[i] : 0;
    if (i < N_NODES) g_dinv[i] = rsqrtf((float)(v + 1));
    sh[t] = v;
    __syncthreads();
#pragma unroll
    for (int off = 1; off < SCAN_BLK; off <<= 1) {
        int tmp = (t >= off) ? sh[t - off] : 0;
        __syncthreads();
        sh[t] += tmp;
        __syncthreads();
    }
    int incl = sh[t];
    if (t == SCAN_BLK - 1) {
        g_bsum[b] = incl;
        __threadfence();
        atomicAdd(&g_scan_done, 1);
    }
    if (t == 0) {
        while (*(volatile int*)&g_scan_done < (int)gridDim.x) {}
    }
    __syncthreads();
    __threadfence();
    if (t < 64) sh2[t] = (t < (int)gridDim.x) ? *(volatile int*)&g_bsum[t] : 0;
    __syncthreads();
#pragma unroll
    for (int off = 1; off < 64; off <<= 1) {
        int tmp = (t >= off && t < 64) ? sh2[t - off] : 0;
        __syncthreads();
        if (t < 64) sh2[t] += tmp;
        __syncthreads();
    }
    int boff = (b > 0) ? sh2[b - 1] : 0;
    if (i < N_NODES) {
        int r = boff + incl - v;
        g_rowptr[i] = r;
        g_cursor[i] = r;
    }
    if (b == 0 && t == 0) g_rowptr[N_NODES] = N_EDGES;
}

// ---------------- fused pack (xh = fp16(dinv*x)) + fill (CSR columns) ----------------
__global__ void k_packfill(const float* __restrict__ x, const int* __restrict__ ei) {
    int bi = blockIdx.x;
    if (bi < PACK_BLOCKS) {
        int t = bi * 256 + threadIdx.x;
        int node = t >> 5;
        float di = g_dinv[node];
        float4 v = ((const float4*)x)[t];
        union { __half2 h[2]; uint2 u; } cv;
        cv.h[0] = __floats2half2_rn(di * v.x, di * v.y);
        cv.h[1] = __floats2half2_rn(di * v.z, di * v.w);
        ((uint2*)g_xh)[t] = cv.u;
    } else {
        int t = (bi - PACK_BLOCKS) * 256 + threadIdx.x;
        if (t < N_EDGES / 4) {
            int4 s = ((const int4*)ei)[t];
            int4 d = ((const int4*)(ei + N_EDGES))[t];
            int p0 = atomicAdd(&g_cursor[d.x], 1);
            int p1 = atomicAdd(&g_cursor[d.y], 1);
            int p2 = atomicAdd(&g_cursor[d.z], 1);
            int p3 = atomicAdd(&g_cursor[d.w], 1);
            g_csrc[p0] = s.x;
            g_csrc[p1] = s.y;
            g_csrc[p2] = s.z;
            g_csrc[p3] = s.w;
        }
    }
}

// ---------------- conv1 gather: fp16 rows, hadd2 pair pre-accum, fp32 accum ----------------
__global__ void k_agg1() {
    int w = (blockIdx.x * blockDim.x + threadIdx.x) >> 5;
    if (w >= N_NODES) return;
    int lane = threadIdx.x & 31;
    int beg = g_rowptr[w], end = g_rowptr[w + 1];
    const uint2* xv = (const uint2*)g_xh;

    float4 acc;
    {   // self loop
        uint2 u = xv[w * 32 + lane];
        float2 f0 = __half22float2(*(__half2*)&u.x);
        float2 f1 = __half22float2(*(__half2*)&u.y);
        acc = make_float4(f0.x, f0.y, f1.x, f1.y);
    }
    int j = beg;
    // align j to 4 for int4 index loads
    int pre = (4 - (j & 3)) & 3;
    if (pre > end - j) pre = end - j;
    for (int p = 0; p < pre; p++, j++) {
        uint2 u = xv[g_csrc[j] * 32 + lane];
        float2 f0 = __half22float2(*(__half2*)&u.x);
        float2 f1 = __half22float2(*(__half2*)&u.y);
        acc.x += f0.x; acc.y += f0.y; acc.z += f1.x; acc.w += f1.y;
    }
    for (; j + 3 < end; j += 4) {
        int4 c4 = *(const int4*)&g_csrc[j];
        uint2 u0 = xv[c4.x * 32 + lane];
        uint2 u1 = xv[c4.y * 32 + lane];
        uint2 u2 = xv[c4.z * 32 + lane];
        uint2 u3 = xv[c4.w * 32 + lane];
        // fp16 pair pre-accumulate (one extra rounding per pair)
        __half2 p0x = __hadd2(*(__half2*)&u0.x, *(__half2*)&u1.x);
        __half2 p0y = __hadd2(*(__half2*)&u0.y, *(__half2*)&u1.y);
        __half2 p1x = __hadd2(*(__half2*)&u2.x, *(__half2*)&u3.x);
        __half2 p1y = __hadd2(*(__half2*)&u2.y, *(__half2*)&u3.y);
        float2 a0 = __half22float2(p0x), b0 = __half22float2(p0y);
        float2 a1 = __half22float2(p1x), b1 = __half22float2(p1y);
        acc.x += a0.x + a1.x;
        acc.y += a0.y + a1.y;
        acc.z += b0.x + b1.x;
        acc.w += b0.y + b1.y;
    }
    for (; j < end; j++) {
        uint2 u = xv[g_csrc[j] * 32 + lane];
        float2 f0 = __half22float2(*(__half2*)&u.x);
        float2 f1 = __half22float2(*(__half2*)&u.y);
        acc.x += f0.x; acc.y += f0.y; acc.z += f1.x; acc.w += f1.y;
    }
    ((float4*)g_S1)[w * 32 + lane] = acc;
}

// ---------------- GEMM1 (tf32 MMA): h1 = relu(dinv*(S1@W1)+b1)  [50000x128]x[128x256]
#define G1_AS 36
#define G1_BS 72
__global__ void k_gemm1(const float* __restrict__ W, const float* __restrict__ b1) {
    __shared__ unsigned As[128 * G1_AS];
    __shared__ unsigned Bs[32 * G1_BS];
    const int tid   = threadIdx.x;
    const int tileM = blockIdx.x * 128;
    const int tileN = blockIdx.y * 64;
    const int warpId = tid >> 5, lane = tid & 31;
    const int warpM = warpId & 3, warpN = warpId >> 2;
    const int gid = lane >> 2, tg = lane & 3;

    float acc[2][4][4] = {};

    for (int k0 = 0; k0 < IN_C; k0 += 32) {
#pragma unroll
        for (int i = 0; i < 4; i++) {
            int idx = tid + i * 256;
            int r   = idx >> 3;
            int c0  = (idx & 7) * 4;
            int grow = tileM + r;
            float4 v = make_float4(0.f,0.f,0.f,0.f);
            if (grow < N_NODES) v = *(const float4*)&g_S1[grow * IN_C + k0 + c0];
            unsigned* a = &As[r * G1_AS + c0];
            a[0]=f2tf32(v.x); a[1]=f2tf32(v.y); a[2]=f2tf32(v.z); a[3]=f2tf32(v.w);
        }
#pragma unroll
        for (int i = 0; i < 2; i++) {
            int idx = tid + i * 256;
            int r   = idx >> 4;
            int c   = (idx & 15) * 4;
            float4 v = *(const float4*)&W[(k0 + r) * HID1 + tileN + c];
            unsigned* b = &Bs[r * G1_BS + c];
            b[0]=f2tf32(v.x); b[1]=f2tf32(v.y); b[2]=f2tf32(v.z); b[3]=f2tf32(v.w);
        }
        __syncthreads();
#pragma unroll
        for (int ks = 0; ks < 32; ks += 8) {
            unsigned a[2][4];
#pragma unroll
            for (int mt = 0; mt < 2; mt++) {
                int rb = warpM * 32 + mt * 16;
                a[mt][0] = As[(rb + gid    ) * G1_AS + ks + tg    ];
                a[mt][1] = As[(rb + gid + 8) * G1_AS + ks + tg    ];
                a[mt][2] = As[(rb + gid    ) * G1_AS + ks + tg + 4];
                a[mt][3] = As[(rb + gid + 8) * G1_AS + ks + tg + 4];
            }
#pragma unroll
            for (int nt = 0; nt < 4; nt++) {
                int cb = warpN * 32 + nt * 8;
                unsigned b0 = Bs[(ks + tg    ) * G1_BS + cb + gid];
                unsigned b1v= Bs[(ks + tg + 4) * G1_BS + cb + gid];
#pragma unroll
                for (int mt = 0; mt < 2; mt++)
                    mma_tf32(acc[mt][nt], a[mt][0], a[mt][1], a[mt][2], a[mt][3], b0, b1v);
            }
        }
        __syncthreads();
    }

#pragma unroll
    for (int mt = 0; mt < 2; mt++) {
        int r0 = tileM + warpM * 32 + mt * 16 + gid;
        int r1 = r0 + 8;
        float d0 = (r0 < N_NODES) ? g_dinv[r0] : 0.f;
        float d1 = (r1 < N_NODES) ? g_dinv[r1] : 0.f;
#pragma unroll
        for (int nt = 0; nt < 4; nt++) {
            int c = tileN + warpN * 32 + nt * 8 + tg * 2;
            float bb0 = b1[c], bb1 = b1[c + 1];
            if (r0 < N_NODES) {
                float2 o;
                o.x = fmaxf(d0 * acc[mt][nt][0] + bb0, 0.f);
                o.y = fmaxf(d0 * acc[mt][nt][1] + bb1, 0.f);
                *(float2*)&g_h1[r0 * HID1 + c] = o;
            }
            if (r1 < N_NODES) {
                float2 o;
                o.x = fmaxf(d1 * acc[mt][nt][2] + bb0, 0.f);
                o.y = fmaxf(d1 * acc[mt][nt][3] + bb1, 0.f);
                *(float2*)&g_h1[r1 * HID1 + c] = o;
            }
        }
    }
}

// ---------------- GEMM2 (tf32 MMA): th = fp16(dinv*(h1@W2))  [50000x256]x[256x32]
#define G2_AS 36
#define G2_BS 72
__global__ void k_gemm2(const float* __restrict__ W2) {
    __shared__ unsigned As[128 * G2_AS];
    __shared__ unsigned Bs[32 * G2_BS];
    const int tid   = threadIdx.x;
    const int tileM = blockIdx.x * 128;
    const int warpId = tid >> 5, lane = tid & 31;
    const int gid = lane >> 2, tg = lane & 3;

    float acc[4][4] = {};

    for (int k0 = 0; k0 < HID1; k0 += 32) {
#pragma unroll
        for (int i = 0; i < 4; i++) {
            int idx = tid + i * 256;
            int r   = idx >> 3;
            int c0  = (idx & 7) * 4;
            int grow = tileM + r;
            float4 v = make_float4(0.f,0.f,0.f,0.f);
            if (grow < N_NODES) v = *(const float4*)&g_h1[grow * HID1 + k0 + c0];
            unsigned* a = &As[r * G2_AS + c0];
            a[0]=f2tf32(v.x); a[1]=f2tf32(v.y); a[2]=f2tf32(v.z); a[3]=f2tf32(v.w);
        }
        {
            int r = tid >> 3;
            int c = (tid & 7) * 4;
            float4 v = *(const float4*)&W2[(k0 + r) * HID2 + c];
            unsigned* b = &Bs[r * G2_BS + c];
            b[0]=f2tf32(v.x); b[1]=f2tf32(v.y); b[2]=f2tf32(v.z); b[3]=f2tf32(v.w);
        }
        __syncthreads();
#pragma unroll
        for (int ks = 0; ks < 32; ks += 8) {
            int rb = warpId * 16;
            unsigned a0 = As[(rb + gid    ) * G2_AS + ks + tg    ];
            unsigned a1 = As[(rb + gid + 8) * G2_AS + ks + tg    ];
            unsigned a2 = As[(rb + gid    ) * G2_AS + ks + tg + 4];
            unsigned a3 = As[(rb + gid + 8) * G2_AS + ks + tg + 4];
#pragma unroll
            for (int nt = 0; nt < 4; nt++) {
                int cb = nt * 8;
                unsigned b0 = Bs[(ks + tg    ) * G2_BS + cb + gid];
                unsigned b1v= Bs[(ks + tg + 4) * G2_BS + cb + gid];
                mma_tf32(acc[nt], a0, a1, a2, a3, b0, b1v);
            }
        }
        __syncthreads();
    }

    int r0 = tileM + warpId * 16 + gid;
    int r1 = r0 + 8;
    float d0 = (r0 < N_NODES) ? g_dinv[r0] : 0.f;
    float d1 = (r1 < N_NODES) ? g_dinv[r1] : 0.f;
#pragma unroll
    for (int nt = 0; nt < 4; nt++) {
        int c = nt * 8 + tg * 2;
        if (r0 < N_NODES)
            ((__half2*)g_th)[r0 * 16 + (c >> 1)] =
                __floats2half2_rn(d0 * acc[nt][0], d0 * acc[nt][1]);
        if (r1 < N_NODES)
            ((__half2*)g_th)[r1 * 16 + (c >> 1)] =
                __floats2half2_rn(d1 * acc[nt][2], d1 * acc[nt][3]);
    }
}

// ---------------- conv2 gather + z: 8 lanes/node, fp16 rows, fp32 accum ----------------
__global__ void k_agg2(const float* __restrict__ b2) {
    int t = blockIdx.x * blockDim.x + threadIdx.x;
    int w = t >> 3;
    if (w >= N_NODES) return;
    int lane = t & 7;
    int beg = g_rowptr[w], end = g_rowptr[w + 1];
    const uint2* tv = (const uint2*)g_th;   // 8 uint2 (4 halves) per row

    float4 acc;
    {   // self loop
        uint2 u = tv[w * 8 + lane];
        float2 f0 = __half22float2(*(__half2*)&u.x);
        float2 f1 = __half22float2(*(__half2*)&u.y);
        acc = make_float4(f0.x, f0.y, f1.x, f1.y);
    }
    int j = beg;
    int pre = (4 - (j & 3)) & 3;
    if (pre > end - j) pre = end - j;
    for (int p = 0; p < pre; p++, j++) {
        uint2 u = tv[g_csrc[j] * 8 + lane];
        float2 f0 = __half22float2(*(__half2*)&u.x);
        float2 f1 = __half22float2(*(__half2*)&u.y);
        acc.x += f0.x; acc.y += f0.y; acc.z += f1.x; acc.w += f1.y;
    }
    for (; j + 3 < end; j += 4) {
        int4 c4 = *(const int4*)&g_csrc[j];
        uint2 u0 = tv[c4.x * 8 + lane];
        uint2 u1 = tv[c4.y * 8 + lane];
        uint2 u2 = tv[c4.z * 8 + lane];
        uint2 u3 = tv[c4.w * 8 + lane];
        __half2 p0x = __hadd2(*(__half2*)&u0.x, *(__half2*)&u1.x);
        __half2 p0y = __hadd2(*(__half2*)&u0.y, *(__half2*)&u1.y);
        __half2 p1x = __hadd2(*(__half2*)&u2.x, *(__half2*)&u3.x);
        __half2 p1y = __hadd2(*(__half2*)&u2.y, *(__half2*)&u3.y);
        float2 a0 = __half22float2(p0x), b0 = __half22float2(p0y);
        float2 a1 = __half22float2(p1x), b1 = __half22float2(p1y);
        acc.x += a0.x + a1.x;
        acc.y += a0.y + a1.y;
        acc.z += b0.x + b1.x;
        acc.w += b0.y + b1.y;
    }
    for (; j < end; j++) {
        uint2 u = tv[g_csrc[j] * 8 + lane];
        float2 f0 = __half22float2(*(__half2*)&u.x);
        float2 f1 = __half22float2(*(__half2*)&u.y);
        acc.x += f0.x; acc.y += f0.y; acc.z += f1.x; acc.w += f1.y;
    }
    float dw = g_dinv[w];
    float4 bb = ((const float4*)b2)[lane];
    float4 o = make_float4(dw * acc.x + bb.x, dw * acc.y + bb.y,
                           dw * acc.z + bb.z, dw * acc.w + bb.w);
    ((float4*)g_z)[w * 8 + lane] = o;
}

// ---------------- decode: 8 lanes per edge, float4 loads ----------------
__global__ void k_decode(const int* __restrict__ eli, float* __restrict__ out) {
    int t = blockIdx.x * blockDim.x + threadIdx.x;
    int k = t >> 3;
    if (k >= N_LABEL) return;
    int lane = t & 7;
    int a = eli[k];
    int b = eli[N_LABEL + k];
    float4 za = ((const float4*)g_z)[a * 8 + lane];
    float4 zb = ((const float4*)g_z)[b * 8 + lane];
    float p = za.x * zb.x + za.y * zb.y + za.z * zb.z + za.w * zb.w;
    p += __shfl_xor_sync(0xffffffffu, p, 4);
    p += __shfl_xor_sync(0xffffffffu, p, 2);
    p += __shfl_xor_sync(0xffffffffu, p, 1);
    if (lane == 0) out[k] = p;
}

// ---------------- launch ----------------
extern "C" void kernel_launch(void* const* d_in, const int* in_sizes, int n_in,
                              void* d_out, int out_size) {
    const float* x   = (const float*)d_in[0];
    const int*   ei  = (const int*)d_in[1];     // int32 (JAX x64 disabled)
    const int*   eli = (const int*)d_in[2];
    const float* W1  = (const float*)d_in[3];
    const float* b1  = (const float*)d_in[4];
    const float* W2  = (const float*)d_in[5];
    const float* b2  = (const float*)d_in[6];
    float* out = (float*)d_out;
    (void)in_sizes; (void)n_in; (void)out_size;

    void* cnt_ptr = nullptr;
    cudaGetSymbolAddress(&cnt_ptr, g_cnt);
    cudaMemsetAsync(cnt_ptr, 0, N_NODES * sizeof(int));

    k_hist    <<<(N_EDGES / 4 + 255) / 256, 256>>>(ei);
    k_scan    <<<N_SCAN_BLOCKS, SCAN_BLK>>>();
    k_packfill<<<PACK_BLOCKS + FILL_BLOCKS, 256>>>(x, ei);

    k_agg1    <<<(N_NODES * 32 + 255) / 256, 256>>>();

    dim3 g1((N_NODES + 127) / 128, HID1 / 64);
    k_gemm1   <<<g1, 256>>>(W1, b1);
    k_gemm2   <<<(N_NODES + 127) / 128, 256>>>(W2);

    k_agg2    <<<(N_NODES * 8 + 255) / 256, 256>>>(b2);
    k_decode  <<<(N_LABEL * 8 + 255) / 256, 256>>>(eli, out);
}

// round 12
// speedup vs baseline: 1.7522x; 1.0329x over previous
#include <cuda_runtime.h>
#include <cuda_fp16.h>

#define N_NODES 50000
#define N_EDGES 1600000
#define N_LABEL 200000
#define IN_C    128
#define HID1    256
#define HID2    32

#define SCAN_BLK 1024
#define N_SCAN_BLOCKS ((N_NODES + SCAN_BLK - 1) / SCAN_BLK)   // 49
#define PACK_BLOCKS   (N_NODES * 32 / 256)                     // 6250
#define FILL_BLOCKS   ((N_EDGES / 4 + 255) / 256)              // 1563

// ---------------- device scratch ----------------
__device__ __align__(256) int    g_cnt   [N_NODES];
__device__ __align__(256) int    g_rowptr[N_NODES + 1];
__device__ __align__(256) int    g_cursor[N_NODES];
__device__ __align__(256) int    g_csrc  [N_EDGES];
__device__ __align__(256) int    g_bsum  [64];
__device__            int        g_scan_done;
__device__ __align__(256) float  g_dinv  [N_NODES];
__device__ __align__(256) __half g_xh    [N_NODES * IN_C];   // fp16 dinv*x
__device__ __align__(256) __half g_s1h   [N_NODES * IN_C];   // fp16 conv1 aggregate
__device__ __align__(256) __half g_h1h   [N_NODES * HID1];   // fp16 hidden
__device__ __align__(256) __half g_th    [N_NODES * HID2];   // fp16 dinv*(h1@W2)
__device__ __align__(256) float  g_z     [N_NODES * HID2];

// ---------------- tf32 helpers ----------------
__device__ __forceinline__ unsigned f2tf32(float f) {
    unsigned r;
    asm("cvt.rna.tf32.f32 %0, %1;" : "=r"(r) : "f"(f));
    return r;
}
__device__ __forceinline__ void mma_tf32(float* c, unsigned a0, unsigned a1,
                                         unsigned a2, unsigned a3,
                                         unsigned b0, unsigned b1) {
    asm volatile(
        "mma.sync.aligned.m16n8k8.row.col.f32.tf32.tf32.f32 "
        "{%0,%1,%2,%3}, {%4,%5,%6,%7}, {%8,%9}, {%0,%1,%2,%3};"
        : "+f"(c[0]), "+f"(c[1]), "+f"(c[2]), "+f"(c[3])
        : "r"(a0), "r"(a1), "r"(a2), "r"(a3), "r"(b0), "r"(b1));
}
// convert uint4 of 8 halves -> 8 tf32 words at dst
__device__ __forceinline__ void h8_to_tf32(unsigned* dst, uint4 u) {
    float2 f0 = __half22float2(*(__half2*)&u.x);
    float2 f1 = __half22float2(*(__half2*)&u.y);
    float2 f2 = __half22float2(*(__half2*)&u.z);
    float2 f3 = __half22float2(*(__half2*)&u.w);
    dst[0] = f2tf32(f0.x); dst[1] = f2tf32(f0.y);
    dst[2] = f2tf32(f1.x); dst[3] = f2tf32(f1.y);
    dst[4] = f2tf32(f2.x); dst[5] = f2tf32(f2.y);
    dst[6] = f2tf32(f3.x); dst[7] = f2tf32(f3.y);
}

// ---------------- hist: 4 edges/thread (also resets scan barrier) ----------------
__global__ void k_hist(const int* __restrict__ ei) {
    if (blockIdx.x == 0 && threadIdx.x == 0) g_scan_done = 0;
    int t = blockIdx.x * blockDim.x + threadIdx.x;
    if (t < N_EDGES / 4) {
        int4 d = ((const int4*)(ei + N_EDGES))[t];
        atomicAdd(&g_cnt[d.x], 1);
        atomicAdd(&g_cnt[d.y], 1);
        atomicAdd(&g_cnt[d.z], 1);
        atomicAdd(&g_cnt[d.w], 1);
    }
}

// ---------------- fused scan: 49 co-resident blocks + spin grid-barrier ----------------
__global__ void k_scan() {
    __shared__ int sh[SCAN_BLK];
    __shared__ int sh2[64];
    const int b = blockIdx.x, t = threadIdx.x;
    int i = b * SCAN_BLK + t;
    int v = (i < N_NODES) ? g_cnt[i] : 0;
    if (i < N_NODES) g_dinv[i] = rsqrtf((float)(v + 1));
    sh[t] = v;
    __syncthreads();
#pragma unroll
    for (int off = 1; off < SCAN_BLK; off <<= 1) {
        int tmp = (t >= off) ? sh[t - off] : 0;
        __syncthreads();
        sh[t] += tmp;
        __syncthreads();
    }
    int incl = sh[t];
    if (t == SCAN_BLK - 1) {
        g_bsum[b] = incl;
        __threadfence();
        atomicAdd(&g_scan_done, 1);
    }
    if (t == 0) {
        while (*(volatile int*)&g_scan_done < (int)gridDim.x) {}
    }
    __syncthreads();
    __threadfence();
    if (t < 64) sh2[t] = (t < (int)gridDim.x) ? *(volatile int*)&g_bsum[t] : 0;
    __syncthreads();
#pragma unroll
    for (int off = 1; off < 64; off <<= 1) {
        int tmp = (t >= off && t < 64) ? sh2[t - off] : 0;
        __syncthreads();
        if (t < 64) sh2[t] += tmp;
        __syncthreads();
    }
    int boff = (b > 0) ? sh2[b - 1] : 0;
    if (i < N_NODES) {
        int r = boff + incl - v;
        g_rowptr[i] = r;
        g_cursor[i] = r;
    }
    if (b == 0 && t == 0) g_rowptr[N_NODES] = N_EDGES;
}

// ---------------- fused pack (xh = fp16(dinv*x)) + fill (CSR columns) ----------------
__global__ void k_packfill(const float* __restrict__ x, const int* __restrict__ ei) {
    int bi = blockIdx.x;
    if (bi < PACK_BLOCKS) {
        int t = bi * 256 + threadIdx.x;
        int node = t >> 5;
        float di = g_dinv[node];
        float4 v = ((const float4*)x)[t];
        union { __half2 h[2]; uint2 u; } cv;
        cv.h[0] = __floats2half2_rn(di * v.x, di * v.y);
        cv.h[1] = __floats2half2_rn(di * v.z, di * v.w);
        ((uint2*)g_xh)[t] = cv.u;
    } else {
        int t = (bi - PACK_BLOCKS) * 256 + threadIdx.x;
        if (t < N_EDGES / 4) {
            int4 s = ((const int4*)ei)[t];
            int4 d = ((const int4*)(ei + N_EDGES))[t];
            int p0 = atomicAdd(&g_cursor[d.x], 1);
            int p1 = atomicAdd(&g_cursor[d.y], 1);
            int p2 = atomicAdd(&g_cursor[d.z], 1);
            int p3 = atomicAdd(&g_cursor[d.w], 1);
            g_csrc[p0] = s.x;
            g_csrc[p1] = s.y;
            g_csrc[p2] = s.z;
            g_csrc[p3] = s.w;
        }
    }
}

// ---------------- conv1 gather: fp16 rows, hadd2 pair pre-accum, fp32 accum, fp16 out
__global__ void k_agg1() {
    int w = (blockIdx.x * blockDim.x + threadIdx.x) >> 5;
    if (w >= N_NODES) return;
    int lane = threadIdx.x & 31;
    int beg = g_rowptr[w], end = g_rowptr[w + 1];
    const uint2* xv = (const uint2*)g_xh;

    float4 acc;
    {   // self loop
        uint2 u = xv[w * 32 + lane];
        float2 f0 = __half22float2(*(__half2*)&u.x);
        float2 f1 = __half22float2(*(__half2*)&u.y);
        acc = make_float4(f0.x, f0.y, f1.x, f1.y);
    }
    int j = beg;
    int pre = (4 - (j & 3)) & 3;
    if (pre > end - j) pre = end - j;
    for (int p = 0; p < pre; p++, j++) {
        uint2 u = xv[g_csrc[j] * 32 + lane];
        float2 f0 = __half22float2(*(__half2*)&u.x);
        float2 f1 = __half22float2(*(__half2*)&u.y);
        acc.x += f0.x; acc.y += f0.y; acc.z += f1.x; acc.w += f1.y;
    }
    for (; j + 3 < end; j += 4) {
        int4 c4 = *(const int4*)&g_csrc[j];
        uint2 u0 = xv[c4.x * 32 + lane];
        uint2 u1 = xv[c4.y * 32 + lane];
        uint2 u2 = xv[c4.z * 32 + lane];
        uint2 u3 = xv[c4.w * 32 + lane];
        __half2 p0x = __hadd2(*(__half2*)&u0.x, *(__half2*)&u1.x);
        __half2 p0y = __hadd2(*(__half2*)&u0.y, *(__half2*)&u1.y);
        __half2 p1x = __hadd2(*(__half2*)&u2.x, *(__half2*)&u3.x);
        __half2 p1y = __hadd2(*(__half2*)&u2.y, *(__half2*)&u3.y);
        float2 a0 = __half22float2(p0x), b0 = __half22float2(p0y);
        float2 a1 = __half22float2(p1x), b1 = __half22float2(p1y);
        acc.x += a0.x + a1.x;
        acc.y += a0.y + a1.y;
        acc.z += b0.x + b1.x;
        acc.w += b0.y + b1.y;
    }
    for (; j < end; j++) {
        uint2 u = xv[g_csrc[j] * 32 + lane];
        float2 f0 = __half22float2(*(__half2*)&u.x);
        float2 f1 = __half22float2(*(__half2*)&u.y);
        acc.x += f0.x; acc.y += f0.y; acc.z += f1.x; acc.w += f1.y;
    }
    union { __half2 h[2]; uint2 u; } cv;
    cv.h[0] = __floats2half2_rn(acc.x, acc.y);
    cv.h[1] = __floats2half2_rn(acc.z, acc.w);
    ((uint2*)g_s1h)[w * 32 + lane] = cv.u;
}

// ---------------- GEMM1 (tf32 MMA, fp16 A in gmem): h1h = fp16(relu(dinv*(S1@W1)+b1))
#define G1_AS 36
#define G1_BS 72
__global__ void k_gemm1(const float* __restrict__ W, const float* __restrict__ b1) {
    __shared__ unsigned As[128 * G1_AS];
    __shared__ unsigned Bs[32 * G1_BS];
    const int tid   = threadIdx.x;
    const int tileM = blockIdx.x * 128;
    const int tileN = blockIdx.y * 64;
    const int warpId = tid >> 5, lane = tid & 31;
    const int warpM = warpId & 3, warpN = warpId >> 2;
    const int gid = lane >> 2, tg = lane & 3;

    float acc[2][4][4] = {};

    for (int k0 = 0; k0 < IN_C; k0 += 32) {
        // A tile 128x32 halves: 512 uint4 slots -> 2 per thread
#pragma unroll
        for (int i = 0; i < 2; i++) {
            int idx = tid + i * 256;
            int r   = idx >> 2;
            int c8  = (idx & 3) * 8;
            int grow = tileM + r;
            uint4 u = make_uint4(0u, 0u, 0u, 0u);
            if (grow < N_NODES) u = *(const uint4*)&g_s1h[grow * IN_C + k0 + c8];
            h8_to_tf32(&As[r * G1_AS + c8], u);
        }
#pragma unroll
        for (int i = 0; i < 2; i++) {
            int idx = tid + i * 256;
            int r   = idx >> 4;
            int c   = (idx & 15) * 4;
            float4 v = *(const float4*)&W[(k0 + r) * HID1 + tileN + c];
            unsigned* b = &Bs[r * G1_BS + c];
            b[0]=f2tf32(v.x); b[1]=f2tf32(v.y); b[2]=f2tf32(v.z); b[3]=f2tf32(v.w);
        }
        __syncthreads();
#pragma unroll
        for (int ks = 0; ks < 32; ks += 8) {
            unsigned a[2][4];
#pragma unroll
            for (int mt = 0; mt < 2; mt++) {
                int rb = warpM * 32 + mt * 16;
                a[mt][0] = As[(rb + gid    ) * G1_AS + ks + tg    ];
                a[mt][1] = As[(rb + gid + 8) * G1_AS + ks + tg    ];
                a[mt][2] = As[(rb + gid    ) * G1_AS + ks + tg + 4];
                a[mt][3] = As[(rb + gid + 8) * G1_AS + ks + tg + 4];
            }
#pragma unroll
            for (int nt = 0; nt < 4; nt++) {
                int cb = warpN * 32 + nt * 8;
                unsigned b0 = Bs[(ks + tg    ) * G1_BS + cb + gid];
                unsigned b1v= Bs[(ks + tg + 4) * G1_BS + cb + gid];
#pragma unroll
                for (int mt = 0; mt < 2; mt++)
                    mma_tf32(acc[mt][nt], a[mt][0], a[mt][1], a[mt][2], a[mt][3], b0, b1v);
            }
        }
        __syncthreads();
    }

#pragma unroll
    for (int mt = 0; mt < 2; mt++) {
        int r0 = tileM + warpM * 32 + mt * 16 + gid;
        int r1 = r0 + 8;
        float d0 = (r0 < N_NODES) ? g_dinv[r0] : 0.f;
        float d1 = (r1 < N_NODES) ? g_dinv[r1] : 0.f;
#pragma unroll
        for (int nt = 0; nt < 4; nt++) {
            int c = tileN + warpN * 32 + nt * 8 + tg * 2;
            float bb0 = b1[c], bb1 = b1[c + 1];
            if (r0 < N_NODES) {
                __half2 o = __floats2half2_rn(
                    fmaxf(d0 * acc[mt][nt][0] + bb0, 0.f),
                    fmaxf(d0 * acc[mt][nt][1] + bb1, 0.f));
                ((__half2*)g_h1h)[(r0 * HID1 + c) >> 1] = o;
            }
            if (r1 < N_NODES) {
                __half2 o = __floats2half2_rn(
                    fmaxf(d1 * acc[mt][nt][2] + bb0, 0.f),
                    fmaxf(d1 * acc[mt][nt][3] + bb1, 0.f));
                ((__half2*)g_h1h)[(r1 * HID1 + c) >> 1] = o;
            }
        }
    }
}

// ---------------- GEMM2 (tf32 MMA, fp16 A in gmem): th = fp16(dinv*(h1@W2))
#define G2_AS 36
#define G2_BS 72
__global__ void k_gemm2(const float* __restrict__ W2) {
    __shared__ unsigned As[128 * G2_AS];
    __shared__ unsigned Bs[32 * G2_BS];
    const int tid   = threadIdx.x;
    const int tileM = blockIdx.x * 128;
    const int warpId = tid >> 5, lane = tid & 31;
    const int gid = lane >> 2, tg = lane & 3;

    float acc[4][4] = {};

    for (int k0 = 0; k0 < HID1; k0 += 32) {
#pragma unroll
        for (int i = 0; i < 2; i++) {
            int idx = tid + i * 256;
            int r   = idx >> 2;
            int c8  = (idx & 3) * 8;
            int grow = tileM + r;
            uint4 u = make_uint4(0u, 0u, 0u, 0u);
            if (grow < N_NODES) u = *(const uint4*)&g_h1h[grow * HID1 + k0 + c8];
            h8_to_tf32(&As[r * G2_AS + c8], u);
        }
        {
            int r = tid >> 3;
            int c = (tid & 7) * 4;
            float4 v = *(const float4*)&W2[(k0 + r) * HID2 + c];
            unsigned* b = &Bs[r * G2_BS + c];
            b[0]=f2tf32(v.x); b[1]=f2tf32(v.y); b[2]=f2tf32(v.z); b[3]=f2tf32(v.w);
        }
        __syncthreads();
#pragma unroll
        for (int ks = 0; ks < 32; ks += 8) {
            int rb = warpId * 16;
            unsigned a0 = As[(rb + gid    ) * G2_AS + ks + tg    ];
            unsigned a1 = As[(rb + gid + 8) * G2_AS + ks + tg    ];
            unsigned a2 = As[(rb + gid    ) * G2_AS + ks + tg + 4];
            unsigned a3 = As[(rb + gid + 8) * G2_AS + ks + tg + 4];
#pragma unroll
            for (int nt = 0; nt < 4; nt++) {
                int cb = nt * 8;
                unsigned b0 = Bs[(ks + tg    ) * G2_BS + cb + gid];
                unsigned b1v= Bs[(ks + tg + 4) * G2_BS + cb + gid];
                mma_tf32(acc[nt], a0, a1, a2, a3, b0, b1v);
            }
        }
        __syncthreads();
    }

    int r0 = tileM + warpId * 16 + gid;
    int r1 = r0 + 8;
    float d0 = (r0 < N_NODES) ? g_dinv[r0] : 0.f;
    float d1 = (r1 < N_NODES) ? g_dinv[r1] : 0.f;
#pragma unroll
    for (int nt = 0; nt < 4; nt++) {
        int c = nt * 8 + tg * 2;
        if (r0 < N_NODES)
            ((__half2*)g_th)[r0 * 16 + (c >> 1)] =
                __floats2half2_rn(d0 * acc[nt][0], d0 * acc[nt][1]);
        if (r1 < N_NODES)
            ((__half2*)g_th)[r1 * 16 + (c >> 1)] =
                __floats2half2_rn(d1 * acc[nt][2], d1 * acc[nt][3]);
    }
}

// ---------------- conv2 gather + z: 8 lanes/node, fp16 rows, fp32 accum ----------------
__global__ void k_agg2(const float* __restrict__ b2) {
    int t = blockIdx.x * blockDim.x + threadIdx.x;
    int w = t >> 3;
    if (w >= N_NODES) return;
    int lane = t & 7;
    int beg = g_rowptr[w], end = g_rowptr[w + 1];
    const uint2* tv = (const uint2*)g_th;

    float4 acc;
    {   // self loop
        uint2 u = tv[w * 8 + lane];
        float2 f0 = __half22float2(*(__half2*)&u.x);
        float2 f1 = __half22float2(*(__half2*)&u.y);
        acc = make_float4(f0.x, f0.y, f1.x, f1.y);
    }
    int j = beg;
    int pre = (4 - (j & 3)) & 3;
    if (pre > end - j) pre = end - j;
    for (int p = 0; p < pre; p++, j++) {
        uint2 u = tv[g_csrc[j] * 8 + lane];
        float2 f0 = __half22float2(*(__half2*)&u.x);
        float2 f1 = __half22float2(*(__half2*)&u.y);
        acc.x += f0.x; acc.y += f0.y; acc.z += f1.x; acc.w += f1.y;
    }
    for (; j + 3 < end; j += 4) {
        int4 c4 = *(const int4*)&g_csrc[j];
        uint2 u0 = tv[c4.x * 8 + lane];
        uint2 u1 = tv[c4.y * 8 + lane];
        uint2 u2 = tv[c4.z * 8 + lane];
        uint2 u3 = tv[c4.w * 8 + lane];
        __half2 p0x = __hadd2(*(__half2*)&u0.x, *(__half2*)&u1.x);
        __half2 p0y = __hadd2(*(__half2*)&u0.y, *(__half2*)&u1.y);
        __half2 p1x = __hadd2(*(__half2*)&u2.x, *(__half2*)&u3.x);
        __half2 p1y = __hadd2(*(__half2*)&u2.y, *(__half2*)&u3.y);
        float2 a0 = __half22float2(p0x), b0 = __half22float2(p0y);
        float2 a1 = __half22float2(p1x), b1 = __half22float2(p1y);
        acc.x += a0.x + a1.x;
        acc.y += a0.y + a1.y;
        acc.z += b0.x + b1.x;
        acc.w += b0.y + b1.y;
    }
    for (; j < end; j++) {
        uint2 u = tv[g_csrc[j] * 8 + lane];
        float2 f0 = __half22float2(*(__half2*)&u.x);
        float2 f1 = __half22float2(*(__half2*)&u.y);
        acc.x += f0.x; acc.y += f0.y; acc.z += f1.x; acc.w += f1.y;
    }
    float dw = g_dinv[w];
    float4 bb = ((const float4*)b2)[lane];
    float4 o = make_float4(dw * acc.x + bb.x, dw * acc.y + bb.y,
                           dw * acc.z + bb.z, dw * acc.w + bb.w);
    ((float4*)g_z)[w * 8 + lane] = o;
}

// ---------------- decode: 8 lanes per edge, float4 loads ----------------
__global__ void k_decode(const int* __restrict__ eli, float* __restrict__ out) {
    int t = blockIdx.x * blockDim.x + threadIdx.x;
    int k = t >> 3;
    if (k >= N_LABEL) return;
    int lane = t & 7;
    int a = eli[k];
    int b = eli[N_LABEL + k];
    float4 za = ((const float4*)g_z)[a * 8 + lane];
    float4 zb = ((const float4*)g_z)[b * 8 + lane];
    float p = za.x * zb.x + za.y * zb.y + za.z * zb.z + za.w * zb.w;
    p += __shfl_xor_sync(0xffffffffu, p, 4);
    p += __shfl_xor_sync(0xffffffffu, p, 2);
    p += __shfl_xor_sync(0xffffffffu, p, 1);
    if (lane == 0) out[k] = p;
}

// ---------------- launch ----------------
extern "C" void kernel_launch(void* const* d_in, const int* in_sizes, int n_in,
                              void* d_out, int out_size) {
    const float* x   = (const float*)d_in[0];
    const int*   ei  = (const int*)d_in[1];     // int32 (JAX x64 disabled)
    const int*   eli = (const int*)d_in[2];
    const float* W1  = (const float*)d_in[3];
    const float* b1  = (const float*)d_in[4];
    const float* W2  = (const float*)d_in[5];
    const float* b2  = (const float*)d_in[6];
    float* out = (float*)d_out;
    (void)in_sizes; (void)n_in; (void)out_size;

    void* cnt_ptr = nullptr;
    cudaGetSymbolAddress(&cnt_ptr, g_cnt);
    cudaMemsetAsync(cnt_ptr, 0, N_NODES * sizeof(int));

    k_hist    <<<(N_EDGES / 4 + 255) / 256, 256>>>(ei);
    k_scan    <<<N_SCAN_BLOCKS, SCAN_BLK>>>();
    k_packfill<<<PACK_BLOCKS + FILL_BLOCKS, 256>>>(x, ei);

    k_agg1    <<<(N_NODES * 32 + 255) / 256, 256>>>();

    dim3 g1((N_NODES + 127) / 128, HID1 / 64);
    k_gemm1   <<<g1, 256>>>(W1, b1);
    k_gemm2   <<<(N_NODES + 127) / 128, 256>>>(W2);

    k_agg2    <<<(N_NODES * 8 + 255) / 256, 256>>>(b2);
    k_decode  <<<(N_LABEL * 8 + 255) / 256, 256>>>(eli, out);
}